// round 17
// baseline (speedup 1.0000x reference)
#include <cuda_runtime.h>
#include <cuda_bf16.h>
#include <cstdint>

// B=512, H=8, C=8192.
//   loss = -sum_{b,c} w'[c] * max(lg2(t ? p : 1-p), -100/ln2)
//   w'[c] = (ln2/C) * sum_h lam[h]*La[h,c]
// Kernel A (PDL-overlapped): computes w into g_w4, zeroes out.
// Kernel B: LDG.256 (ld.global.v8.b32, Blackwell 256-bit loads) — halves the
// LDG warp-instruction count, which the session's audit identifies as the
// binding constraint (LSU dispatch floor 4 cyc/LDG: 3546 LDG/SMSP ~= 7.2us,
// invariant across all R1-R15 variants). Each thread: 4 yp + 4 yt float8
// granules at stride NT (== 0 mod C8 -> one 8-wide weight), product-of-4 log
// batching (8 MUFU/thread), predicated rare-path zero clamp (R12 semantics).

#define B_DIM 512
#define H_DIM 8
#define C_DIM 8192
#define C8 (C_DIM / 8)                // 1024 float8-granules per row
#define NT 131072                     // total threads in kernel B
#define NBLOCKS (NT / 256)            // 512
// N8 = B*C/8 = 524288 = NT * 4  -> 4 float8-pairs per thread

#define LOG2_CLAMP (-144.26950408889634f)   // -100 / ln2
#define LN2 (0.6931471805599453f)

__device__ float g_w4[C_DIM];         // per-class weight * ln2 / C

// ---------------------------------------------------------------------------
// Kernel A: trigger B immediately, then compute w and zero the output.
// ---------------------------------------------------------------------------
__global__ void multibce_weights_kernel(const float* __restrict__ La,
                                        const float* __restrict__ lam,
                                        float* __restrict__ out) {
    cudaTriggerProgrammaticLaunchCompletion();
    int c = blockIdx.x * blockDim.x + threadIdx.x;
    if (c < C_DIM) {
        float s = 0.0f;
#pragma unroll
        for (int h = 0; h < H_DIM; ++h) {
            s = fmaf(lam[h], La[h * C_DIM + c], s);
        }
        g_w4[c] = s * (LN2 / (float)C_DIM);
    }
    if (c == 0) out[0] = 0.0f;
}

// ---------------------------------------------------------------------------
// Kernel B
// ---------------------------------------------------------------------------
// 256-bit load: 8 consecutive floats (32B-aligned: base + tid*32).
__device__ __forceinline__ void ldg256(const float* g, float* v) {
    unsigned r0, r1, r2, r3, r4, r5, r6, r7;
    asm volatile("ld.global.v8.b32 {%0,%1,%2,%3,%4,%5,%6,%7}, [%8];"
                 : "=r"(r0), "=r"(r1), "=r"(r2), "=r"(r3),
                   "=r"(r4), "=r"(r5), "=r"(r6), "=r"(r7)
                 : "l"(g));
    v[0] = __uint_as_float(r0); v[1] = __uint_as_float(r1);
    v[2] = __uint_as_float(r2); v[3] = __uint_as_float(r3);
    v[4] = __uint_as_float(r4); v[5] = __uint_as_float(r5);
    v[6] = __uint_as_float(r6); v[7] = __uint_as_float(r7);
}

// x = t ? p : 1-p (exact for binary t). Only exact zeros need the clamp;
// substitute 1.0 and count the -144.27 penalty (R12-proven predicated path).
__device__ __forceinline__ float xval(float p, float t, float& pen) {
    float x = fmaf(p, 2.0f * t - 1.0f, 1.0f - t);
    if (x < 1e-40f) { pen += 1.0f; x = 1.0f; }
    return x;
}

__global__ void __launch_bounds__(256)
multibce_reduce_kernel(const float* __restrict__ yp,
                       const float* __restrict__ yt,
                       float* __restrict__ out) {
    const int tid = blockIdx.x * 256 + threadIdx.x;   // float8-granule index
    const int c8  = tid & (C8 - 1);

    float pr[8], pen[8], s[8];
#pragma unroll
    for (int k = 0; k < 8; ++k) { pr[k] = 1.0f; pen[k] = 0.0f; }

    // 2 chunks x 2 float8-pairs: 4 LDG.256 front-batched per chunk.
#pragma unroll 1
    for (int jc = 0; jc < 2; ++jc) {
        float pa[8], pb[8], ta[8], tb[8];
        const float* ypa = yp + (size_t)(tid + (2 * jc)     * NT) * 8;
        const float* ypb = yp + (size_t)(tid + (2 * jc + 1) * NT) * 8;
        const float* yta = yt + (size_t)(tid + (2 * jc)     * NT) * 8;
        const float* ytb = yt + (size_t)(tid + (2 * jc + 1) * NT) * 8;
        ldg256(ypa, pa);
        ldg256(ypb, pb);
        ldg256(yta, ta);
        ldg256(ytb, tb);
#pragma unroll
        for (int k = 0; k < 8; ++k) {
            pr[k] *= xval(pa[k], ta[k], pen[k]) * xval(pb[k], tb[k], pen[k]);
        }
    }

    // One MUFU per component (product of 4 nonzero x's >= 2^-96: normal).
#pragma unroll
    for (int k = 0; k < 8; ++k) {
        s[k] = fmaf(pen[k], LOG2_CLAMP, __log2f(pr[k]));
    }

    // Wait for kernel A, then apply weights (8 classes per thread).
    cudaGridDependencySynchronize();
    const float4* w4 = reinterpret_cast<const float4*>(g_w4);
    float4 w0 = w4[2 * c8];
    float4 w1 = w4[2 * c8 + 1];
    float acc = fmaf(w0.x, s[0], fmaf(w0.y, s[1],
                fmaf(w0.z, s[2], fmaf(w0.w, s[3],
                fmaf(w1.x, s[4], fmaf(w1.y, s[5],
                fmaf(w1.z, s[6], w1.w * s[7])))))));

    // warp reduce
#pragma unroll
    for (int o = 16; o > 0; o >>= 1)
        acc += __shfl_xor_sync(0xFFFFFFFFu, acc, o);

    // block reduce
    __shared__ float smem[8];
    int lane = threadIdx.x & 31;
    int warp = threadIdx.x >> 5;
    if (lane == 0) smem[warp] = acc;
    __syncthreads();
    if (warp == 0) {
        acc = (lane < 8) ? smem[lane] : 0.0f;
#pragma unroll
        for (int o = 4; o > 0; o >>= 1)
            acc += __shfl_xor_sync(0xFFFFFFFFu, acc, o);
        if (lane == 0) atomicAdd(out, -acc);   // loss = -sum
    }
}

// ---------------------------------------------------------------------------
extern "C" void kernel_launch(void* const* d_in, const int* in_sizes, int n_in,
                              void* d_out, int out_size) {
    const float* y_pred = (const float*)d_in[0];
    const float* y_true = (const float*)d_in[1];
    const float* La     = (const float*)d_in[2];
    const float* lam    = (const float*)d_in[3];
    float* out = (float*)d_out;

    multibce_weights_kernel<<<(C_DIM + 255) / 256, 256>>>(La, lam, out);

    cudaLaunchConfig_t cfg = {};
    cfg.gridDim  = dim3(NBLOCKS);
    cfg.blockDim = dim3(256);
    cfg.dynamicSmemBytes = 0;
    cfg.stream = 0;
    cudaLaunchAttribute attr[1];
    attr[0].id = cudaLaunchAttributeProgrammaticStreamSerialization;
    attr[0].val.programmaticStreamSerializationAllowed = 1;
    cfg.attrs = attr;
    cfg.numAttrs = 1;
    cudaLaunchKernelEx(&cfg, multibce_reduce_kernel,
                       y_pred, y_true, out);
}